// round 12
// baseline (speedup 1.0000x reference)
#include <cuda_runtime.h>
#include <math.h>
#include <stdint.h>

#define BB 16384
#define CC 2048
#define DDIM 128
#define TILE_B 128          // samples per tile
#define NTILE (BB / TILE_B) // 128 tiles per side
#define CSPLIT 4
#define CUNIT (CC / CSPLIT) // 512 centroids per unit
#define NCH_U (CUNIT / 64)  // 8 chunks of 64
#define ROWB 128            // bytes per smem row (128 int8)
#define LN2F 0.6931471805599453f
#define INVQ 6.2000124e-5f  // 1/(127*127)
#define MAGICI 0x4B400000
#define MAGICF 12582912.0f
#define NPOS (2 * NTILE)    // 256 pos-tail completions total

// ---------------- scratch ----------------
__device__ __align__(16) signed char g_Mb[2 * CC * DDIM];  // s8 M, row-major
__device__ float g_S[2 * BB];            // per-sample S (atomic-accumulated)
__device__ float g_part[NPOS];           // per-tile partials
__device__ unsigned int g_tilecnt[NPOS]; // units finished per tile
__device__ unsigned int g_cnt;           // pos-tails finished

// ---------------- smem layout (bytes) ----------------
#define SM_F     0
#define SM_M0    16384
#define SM_M1    24576
#define SM_IC    32768       // 512 floats
#define SM_RED   34816       // 128 floats
#define SM_WS    35328       // 8 floats
#define SM_FLAG  35360
#define SM_FLAG2 35364
#define SM_TOT   35392

__device__ __forceinline__ uint32_t smem_u32(const void* p) {
    uint32_t a;
    asm("{ .reg .u64 t; cvta.to.shared.u64 t, %1; cvt.u32.u64 %0, t; }" : "=r"(a) : "l"(p));
    return a;
}
__device__ __forceinline__ float ex2f(float x) {
    float y; asm("ex2.approx.f32 %0, %1;" : "=f"(y) : "f"(x)); return y;
}
__device__ __forceinline__ void ldsm_x4(uint32_t& r0, uint32_t& r1, uint32_t& r2,
                                        uint32_t& r3, uint32_t addr) {
    asm volatile("ldmatrix.sync.aligned.m8n8.x4.shared.b16 {%0,%1,%2,%3}, [%4];"
                 : "=r"(r0), "=r"(r1), "=r"(r2), "=r"(r3) : "r"(addr));
}
__device__ __forceinline__ void mma_s8(int& c0, int& c1, int& c2, int& c3,
                                       uint32_t a0, uint32_t a1, uint32_t a2, uint32_t a3,
                                       uint32_t b0, uint32_t b1) {
    asm volatile("mma.sync.aligned.m16n8k32.row.col.s32.s8.s8.s32 "
                 "{%0,%1,%2,%3}, {%4,%5,%6,%7}, {%8,%9}, {%0,%1,%2,%3};"
                 : "+r"(c0), "+r"(c1), "+r"(c2), "+r"(c3)
                 : "r"(a0), "r"(a1), "r"(a2), "r"(a3), "r"(b0), "r"(b1));
}
#define CP_ASYNC16(dst, src) \
    asm volatile("cp.async.cg.shared.global [%0], [%1], 16;" :: "r"(dst), "l"(src) : "memory")
#define CP_COMMIT() asm volatile("cp.async.commit_group;" ::: "memory")
#define CP_WAIT1()  asm volatile("cp.async.wait_group 1;" ::: "memory")
#define CP_WAIT0()  asm volatile("cp.async.wait_group 0;" ::: "memory")

__device__ __forceinline__ uint32_t pack_s8x4(float4 v) {
    int a = __float2int_rn(v.x * 127.f), b = __float2int_rn(v.y * 127.f);
    int c = __float2int_rn(v.z * 127.f), d = __float2int_rn(v.w * 127.f);
    return (a & 255) | ((b & 255) << 8) | ((c & 255) << 16) | ((d & 255) << 24);
}

// ---------------- prep: M fp32 -> s8 + zero accumulators ----------------
__global__ __launch_bounds__(256)
void convM_kernel(const float* __restrict__ M0, const float* __restrict__ M1)
{
    int gid = blockIdx.x * 256 + threadIdx.x;          // 0..32767
    int i = gid * 16;
    const int n = CC * DDIM;
    const float* src = (i < n) ? M0 : M1;
    int off = (i < n) ? i : i - n;
    float4 a = *reinterpret_cast<const float4*>(src + off);
    float4 b = *reinterpret_cast<const float4*>(src + off + 4);
    float4 c = *reinterpret_cast<const float4*>(src + off + 8);
    float4 d = *reinterpret_cast<const float4*>(src + off + 12);
    uint4 w;
    w.x = pack_s8x4(a); w.y = pack_s8x4(b);
    w.z = pack_s8x4(c); w.w = pack_s8x4(d);
    *reinterpret_cast<uint4*>(g_Mb + i) = w;

    g_S[gid] = 0.f;                                    // 2*BB = 32768 exactly
    if (gid < NPOS) g_tilecnt[gid] = 0u;
    if (gid == 0) g_cnt = 0u;
}

// ---------------- main: one C-split unit per CTA ----------------
__global__ __launch_bounds__(256, 2)
void main_kernel(const float* __restrict__ features,
                 const float* __restrict__ features_I,
                 const float* __restrict__ M0,
                 const float* __restrict__ M1,
                 const float* __restrict__ conc0,
                 const float* __restrict__ conc1,
                 const int* __restrict__ lab0,
                 const int* __restrict__ lab1,
                 const int* __restrict__ lbp,
                 float* __restrict__ out)
{
    extern __shared__ __align__(1024) unsigned char smem[];
    const uint32_t sb = smem_u32(smem);
    const int tid  = threadIdx.x;
    const int wid  = tid >> 5;
    const int lane = tid & 31;
    const int wm   = wid >> 1;
    const int wn   = wid & 1;
    const int side = blockIdx.y;
    const int tile = blockIdx.x >> 2;     // 0..127
    const int cseg = blockIdx.x & 3;      // 0..3

    const float* __restrict__ F    = side ? features : features_I;
    const float* __restrict__ Mf   = side ? M1 : M0;
    const float* __restrict__ conc = side ? conc1 : conc0;
    const int*   __restrict__ lab  = side ? lab1 : lab0;
    const signed char* __restrict__ Msrc =
        g_Mb + (size_t)side * CC * DDIM + (size_t)cseg * CUNIT * DDIM;

    float* __restrict__ ic  = reinterpret_cast<float*>(smem + SM_IC);
    float* __restrict__ red = reinterpret_cast<float*>(smem + SM_RED);
    float* __restrict__ ws  = reinterpret_cast<float*>(smem + SM_WS);
    unsigned int* __restrict__ flg  = reinterpret_cast<unsigned int*>(smem + SM_FLAG);
    unsigned int* __restrict__ flg2 = reinterpret_cast<unsigned int*>(smem + SM_FLAG2);

    // segment ic = log2(e)/conc
    #pragma unroll
    for (int i = tid; i < CUNIT; i += 256)
        ic[i] = 1.4426950408889634f / conc[cseg * CUNIT + i];
    if (tid < TILE_B) red[tid] = 0.f;

    // F tile: fp32 -> s8 swizzled
    {
        const float* Fp = F + (size_t)tile * TILE_B * DDIM;
        #pragma unroll
        for (int j = 0; j < 4; j++) {
            int u   = tid + j * 256;
            int row = u >> 3, un = u & 7;
            const float4* p = reinterpret_cast<const float4*>(Fp + row * DDIM + un * 16);
            uint4 w;
            w.x = pack_s8x4(p[0]); w.y = pack_s8x4(p[1]);
            w.z = pack_s8x4(p[2]); w.w = pack_s8x4(p[3]);
            *reinterpret_cast<uint4*>(smem + SM_F + row * ROWB + ((un ^ (row & 7)) << 4)) = w;
        }
    }

    // prefetch chunk 0
    {
        #pragma unroll
        for (int j = 0; j < 2; j++) {
            int u = tid + j * 256;
            int row = u >> 3, un = u & 7;
            CP_ASYNC16(sb + SM_M0 + row * ROWB + ((un ^ (row & 7)) << 4),
                       Msrc + row * DDIM + un * 16);
        }
        CP_COMMIT();
    }

    // ldmatrix geometry
    const int j8 = lane & 7, g = lane >> 3;
    const int arow = wm * 32 + ((g & 1) << 3) + j8;
    const int ap   = g >> 1;
    const int brow = ((g >> 1) << 3) + j8;
    const int bp   = g & 1;
    const uint32_t a_base = sb + SM_F + arow * ROWB;
    const int a_swz = arow & 7;
    const int b_swz = brow & 7;
    const uint32_t b_off0 = (wn * 32 + brow) * ROWB;
    const uint32_t b_off1 = (wn * 32 + 16 + brow) * ROWB;

    __syncthreads();

    uint32_t afr[2][4][4];
    #pragma unroll
    for (int mt = 0; mt < 2; mt++)
        #pragma unroll
        for (int ks = 0; ks < 4; ks++)
            ldsm_x4(afr[mt][ks][0], afr[mt][ks][1], afr[mt][ks][2], afr[mt][ks][3],
                    a_base + mt * 16 * ROWB + ((((ks << 1) + ap) ^ a_swz) << 4));

    float rsum[4] = {0.f, 0.f, 0.f, 0.f};

    for (int i = 0; i < NCH_U; i++) {
        const int s = i & 1;
        if (i + 1 < NCH_U) {
            const signed char* Mc = Msrc + (size_t)(i + 1) * 64 * DDIM;
            const uint32_t dst = sb + (s ? SM_M0 : SM_M1);
            #pragma unroll
            for (int j = 0; j < 2; j++) {
                int u = tid + j * 256;
                int row = u >> 3, un = u & 7;
                CP_ASYNC16(dst + row * ROWB + ((un ^ (row & 7)) << 4),
                           Mc + row * DDIM + un * 16);
            }
            CP_COMMIT();
            CP_WAIT1();
        } else {
            CP_WAIT0();
        }
        __syncthreads();

        const uint32_t mb = sb + (s ? SM_M1 : SM_M0);

        int c[2][4][4];
        #pragma unroll
        for (int mt = 0; mt < 2; mt++)
            #pragma unroll
            for (int nt = 0; nt < 4; nt++)
                #pragma unroll
                for (int q = 0; q < 4; q++) c[mt][nt][q] = MAGICI;

        #pragma unroll
        for (int ks = 0; ks < 4; ks++) {
            uint32_t b[2][4];
            const uint32_t uo = (((ks << 1) + bp) ^ b_swz) << 4;
            ldsm_x4(b[0][0], b[0][1], b[0][2], b[0][3], mb + b_off0 + uo);
            ldsm_x4(b[1][0], b[1][1], b[1][2], b[1][3], mb + b_off1 + uo);
            #pragma unroll
            for (int mt = 0; mt < 2; mt++) {
                #pragma unroll
                for (int h = 0; h < 2; h++) {
                    mma_s8(c[mt][h*2+0][0], c[mt][h*2+0][1], c[mt][h*2+0][2], c[mt][h*2+0][3],
                           afr[mt][ks][0], afr[mt][ks][1], afr[mt][ks][2], afr[mt][ks][3],
                           b[h][0], b[h][1]);
                    mma_s8(c[mt][h*2+1][0], c[mt][h*2+1][1], c[mt][h*2+1][2], c[mt][h*2+1][3],
                           afr[mt][ks][0], afr[mt][ks][1], afr[mt][ks][2], afr[mt][ks][3],
                           b[h][2], b[h][3]);
                }
            }
        }
        __syncthreads();

        const int colbase = i * 64 + wn * 32 + ((lane & 3) << 1);   // local to segment
        float2 sv[4], bv[4];
        #pragma unroll
        for (int nt = 0; nt < 4; nt++) {
            float2 v = *reinterpret_cast<const float2*>(ic + colbase + nt * 8);
            sv[nt].x = v.x * INVQ;          sv[nt].y = v.y * INVQ;
            bv[nt].x = -MAGICF * sv[nt].x;  bv[nt].y = -MAGICF * sv[nt].y;
        }
        #pragma unroll
        for (int mt = 0; mt < 2; mt++)
            #pragma unroll
            for (int nt = 0; nt < 4; nt++) {
                rsum[mt*2+0] += ex2f(fmaf(__int_as_float(c[mt][nt][0]), sv[nt].x, bv[nt].x))
                              + ex2f(fmaf(__int_as_float(c[mt][nt][1]), sv[nt].y, bv[nt].y));
                rsum[mt*2+1] += ex2f(fmaf(__int_as_float(c[mt][nt][2]), sv[nt].x, bv[nt].x))
                              + ex2f(fmaf(__int_as_float(c[mt][nt][3]), sv[nt].y, bv[nt].y));
            }
    }

    // reduce unit row-sums
    #pragma unroll
    for (int i = 0; i < 4; i++) {
        rsum[i] += __shfl_xor_sync(0xFFFFFFFFu, rsum[i], 1);
        rsum[i] += __shfl_xor_sync(0xFFFFFFFFu, rsum[i], 2);
    }
    if ((lane & 3) == 0) {
        const int r0 = wm * 32 + (lane >> 2);
        atomicAdd(red + r0 + 0,  rsum[0]);
        atomicAdd(red + r0 + 8,  rsum[1]);
        atomicAdd(red + r0 + 16, rsum[2]);
        atomicAdd(red + r0 + 24, rsum[3]);
    }
    __syncthreads();

    // accumulate unit S into global
    if (tid < TILE_B)
        atomicAdd(g_S + side * BB + tile * TILE_B + tid, red[tid]);
    __threadfence();
    if (tid == 0) {
        unsigned int v = atomicAdd(&g_tilecnt[side * NTILE + tile], 1u);
        *flg = (v == CSPLIT - 1) ? 1u : 0u;
    }
    __syncthreads();

    if (*flg) {
        __threadfence();   // order: all units' g_S writes visible
        // pos tail for this tile (exact fp32)
        float psum = 0.f;
        const int b0 = tile * TILE_B;
        #pragma unroll 4
        for (int j = 0; j < 16; j++) {
            const int bl  = wid * 16 + j;
            const int bgl = b0 + bl;
            const int l = lab[bgl];
            float4 f = reinterpret_cast<const float4*>(F + (size_t)bgl * DDIM)[lane];
            float4 m = reinterpret_cast<const float4*>(Mf + (size_t)l * DDIM)[lane];
            float d = f.x * m.x + f.y * m.y + f.z * m.z + f.w * m.w;
            #pragma unroll
            for (int o = 16; o > 0; o >>= 1) d += __shfl_xor_sync(0xFFFFFFFFu, d, o);
            if (lane == 0) {
                float S = *((volatile float*)g_S + side * BB + bgl);
                psum += d / conc[l] - logf(S);
            }
        }
        if (lane == 0) ws[wid] = psum;
        __syncthreads();
        if (tid == 0) {
            float s = 0.f;
            #pragma unroll
            for (int i = 0; i < 8; i++) s += ws[i];
            g_part[side * NTILE + tile] = s;
            __threadfence();
            unsigned int v2 = atomicAdd(&g_cnt, 1u);
            *flg2 = (v2 == NPOS - 1) ? 1u : 0u;
        }
        __syncthreads();

        if (*flg2) {
            __threadfence();
            float* smr = ic;   // reuse (512 floats fits)
            smr[tid] = *((volatile float*)g_part + tid);   // 256 partials
            __syncthreads();
            for (int st = 128; st > 0; st >>= 1) {
                if (tid < st) smr[tid] += smr[tid + st];
                __syncthreads();
            }
            if (tid == 0) {
                int iv = lbp[0];
                float lbv = (iv > 1000000 || iv < -1000000) ? __int_as_float(iv) : (float)iv;
                out[0] = (-lbv) * 0.5f / (float)BB * smr[0];
            }
        }
    }
}

// ---------------- launch ----------------
extern "C" void kernel_launch(void* const* d_in, const int* in_sizes, int n_in,
                              void* d_out, int out_size)
{
    const float* features       = (const float*)d_in[0];
    const float* features_I     = (const float*)d_in[1];
    const float* M_kmeans       = (const float*)d_in[2];
    const float* M_kmeans_I     = (const float*)d_in[3];
    const float* concentrations = (const float*)d_in[4];
    const float* concentr_I     = (const float*)d_in[5];
    const int*   labels         = (const int*)d_in[6];
    const int*   labels_I       = (const int*)d_in[7];
    const int*   lb             = (n_in > 8) ? (const int*)d_in[8] : nullptr;
    float* out = (float*)d_out;

    convM_kernel<<<(2 * CC * DDIM / 16) / 256, 256>>>(M_kmeans, M_kmeans_I);

    cudaFuncSetAttribute(main_kernel,
                         cudaFuncAttributeMaxDynamicSharedMemorySize, SM_TOT);
    main_kernel<<<dim3(NTILE * CSPLIT, 2), 256, SM_TOT>>>(
        features, features_I, M_kmeans, M_kmeans_I,
        concentrations, concentr_I, labels, labels_I, lb, out);
}

// round 14
// speedup vs baseline: 1.4416x; 1.4416x over previous
#include <cuda_runtime.h>
#include <cuda_fp16.h>
#include <math.h>
#include <stdint.h>

#define BB 16384
#define CC 2048
#define DDIM 128
#define TILE_B 128          // samples per CTA
#define TILE_C 64           // centroids per chunk
#define NCH (CC / TILE_C)   // 32 chunks
#define ROWB 128            // bytes per smem row (128 int8)
#define LN2F 0.6931471805599453f
#define INVQ 6.2000124e-5f  // 1/(127*127)
#define MAGICI 0x4B400000   // bits of 12582912.0f
#define MAGICF 12582912.0f
#define NBLK (2 * (BB / TILE_B))   // 256 CTAs total

// ---------------- scratch ----------------
__device__ __align__(16) signed char g_Mb[2 * CC * DDIM];  // s8 M, row-major
__device__ float g_part[NBLK];
__device__ unsigned int g_cnt;

// ---------------- smem layout (bytes) ----------------
#define SM_F    0
#define SM_M0   16384
#define SM_M1   24576
#define SM_IC   32768
#define SM_RED  40960
#define SM_WS   41472
#define SM_FLAG 41504
#define SM_TOT  41536

__device__ __forceinline__ uint32_t smem_u32(const void* p) {
    uint32_t a;
    asm("{ .reg .u64 t; cvta.to.shared.u64 t, %1; cvt.u32.u64 %0, t; }" : "=r"(a) : "l"(p));
    return a;
}
// packed-half exp2: two values per MUFU slot
__device__ __forceinline__ uint32_t ex2_h2(uint32_t x) {
    uint32_t y; asm("ex2.approx.f16x2 %0, %1;" : "=r"(y) : "r"(x)); return y;
}
__device__ __forceinline__ uint32_t pack_h2(float lo, float hi) {
    uint32_t d; asm("cvt.rn.f16x2.f32 %0, %1, %2;" : "=r"(d) : "f"(hi), "f"(lo)); return d;
}
__device__ __forceinline__ uint32_t hadd2u(uint32_t a, uint32_t b) {
    uint32_t d; asm("add.rn.f16x2 %0, %1, %2;" : "=r"(d) : "r"(a), "r"(b)); return d;
}
__device__ __forceinline__ void ldsm_x4(uint32_t& r0, uint32_t& r1, uint32_t& r2,
                                        uint32_t& r3, uint32_t addr) {
    asm volatile("ldmatrix.sync.aligned.m8n8.x4.shared.b16 {%0,%1,%2,%3}, [%4];"
                 : "=r"(r0), "=r"(r1), "=r"(r2), "=r"(r3) : "r"(addr));
}
__device__ __forceinline__ void mma_s8(int& c0, int& c1, int& c2, int& c3,
                                       uint32_t a0, uint32_t a1, uint32_t a2, uint32_t a3,
                                       uint32_t b0, uint32_t b1) {
    asm volatile("mma.sync.aligned.m16n8k32.row.col.s32.s8.s8.s32 "
                 "{%0,%1,%2,%3}, {%4,%5,%6,%7}, {%8,%9}, {%0,%1,%2,%3};"
                 : "+r"(c0), "+r"(c1), "+r"(c2), "+r"(c3)
                 : "r"(a0), "r"(a1), "r"(a2), "r"(a3), "r"(b0), "r"(b1));
}
#define CP_ASYNC16(dst, src) \
    asm volatile("cp.async.cg.shared.global [%0], [%1], 16;" :: "r"(dst), "l"(src) : "memory")
#define CP_COMMIT() asm volatile("cp.async.commit_group;" ::: "memory")
#define CP_WAIT1()  asm volatile("cp.async.wait_group 1;" ::: "memory")
#define CP_WAIT0()  asm volatile("cp.async.wait_group 0;" ::: "memory")

__device__ __forceinline__ uint32_t pack_s8x4(float4 v) {
    int a = __float2int_rn(v.x * 127.f), b = __float2int_rn(v.y * 127.f);
    int c = __float2int_rn(v.z * 127.f), d = __float2int_rn(v.w * 127.f);
    return (a & 255) | ((b & 255) << 8) | ((c & 255) << 16) | ((d & 255) << 24);
}

// ---------------- prep: M fp32 -> s8 row-major ----------------
__global__ __launch_bounds__(256)
void convM_kernel(const float* __restrict__ M0, const float* __restrict__ M1)
{
    int i = (blockIdx.x * 256 + threadIdx.x) * 16;
    const int n = CC * DDIM;
    const float* src = (i < n) ? M0 : M1;
    int off = (i < n) ? i : i - n;
    float4 a = *reinterpret_cast<const float4*>(src + off);
    float4 b = *reinterpret_cast<const float4*>(src + off + 4);
    float4 c = *reinterpret_cast<const float4*>(src + off + 8);
    float4 d = *reinterpret_cast<const float4*>(src + off + 12);
    uint4 w;
    w.x = pack_s8x4(a); w.y = pack_s8x4(b);
    w.z = pack_s8x4(c); w.w = pack_s8x4(d);
    *reinterpret_cast<uint4*>(g_Mb + i) = w;
}

// ---------------- main: s8 GEMM + f16x2 exp + row-sum + positive + reduction ----------------
__global__ __launch_bounds__(256, 2)
void main_kernel(const float* __restrict__ features,
                 const float* __restrict__ features_I,
                 const float* __restrict__ M0,
                 const float* __restrict__ M1,
                 const float* __restrict__ conc0,
                 const float* __restrict__ conc1,
                 const int* __restrict__ lab0,
                 const int* __restrict__ lab1,
                 const int* __restrict__ lbp,
                 float* __restrict__ out)
{
    extern __shared__ __align__(1024) unsigned char smem[];
    const uint32_t sb = smem_u32(smem);
    const int tid  = threadIdx.x;
    const int wid  = tid >> 5;
    const int lane = tid & 31;
    const int wm   = wid >> 1;
    const int wn   = wid & 1;
    const int side = blockIdx.y;
    const int bx   = blockIdx.x;

    const float* __restrict__ F    = side ? features : features_I;
    const float* __restrict__ Mf   = side ? M1 : M0;
    const float* __restrict__ conc = side ? conc1 : conc0;
    const int*   __restrict__ lab  = side ? lab1 : lab0;
    const signed char* __restrict__ Msrc = g_Mb + (size_t)side * CC * DDIM;

    float* __restrict__ ic  = reinterpret_cast<float*>(smem + SM_IC);
    float* __restrict__ red = reinterpret_cast<float*>(smem + SM_RED);
    float* __restrict__ ws  = reinterpret_cast<float*>(smem + SM_WS);
    unsigned int* __restrict__ flg = reinterpret_cast<unsigned int*>(smem + SM_FLAG);

    #pragma unroll
    for (int i = tid; i < CC; i += 256) ic[i] = 1.4426950408889634f / conc[i];
    if (tid < TILE_B) red[tid] = 0.f;

    // F tile: fp32 -> s8 into swizzled smem
    {
        const float* Fp = F + (size_t)bx * TILE_B * DDIM;
        #pragma unroll
        for (int j = 0; j < 4; j++) {
            int u   = tid + j * 256;
            int row = u >> 3, un = u & 7;
            const float4* p = reinterpret_cast<const float4*>(Fp + row * DDIM + un * 16);
            uint4 w;
            w.x = pack_s8x4(p[0]); w.y = pack_s8x4(p[1]);
            w.z = pack_s8x4(p[2]); w.w = pack_s8x4(p[3]);
            *reinterpret_cast<uint4*>(smem + SM_F + row * ROWB + ((un ^ (row & 7)) << 4)) = w;
        }
    }

    // prefetch chunk 0
    {
        #pragma unroll
        for (int j = 0; j < 2; j++) {
            int u = tid + j * 256;
            int row = u >> 3, un = u & 7;
            CP_ASYNC16(sb + SM_M0 + row * ROWB + ((un ^ (row & 7)) << 4),
                       Msrc + row * DDIM + un * 16);
        }
        CP_COMMIT();
    }

    // per-thread ldmatrix geometry
    const int j8 = lane & 7, g = lane >> 3;
    const int arow = wm * 32 + ((g & 1) << 3) + j8;
    const int ap   = g >> 1;
    const int brow = ((g >> 1) << 3) + j8;
    const int bp   = g & 1;
    const uint32_t a_base = sb + SM_F + arow * ROWB;
    const int a_swz = arow & 7;
    const int b_swz = brow & 7;
    const uint32_t b_off0 = (wn * 32 + brow) * ROWB;
    const uint32_t b_off1 = (wn * 32 + 16 + brow) * ROWB;

    __syncthreads();

    // hoist A fragments: 2 mt x 4 k32-slices x 4 regs
    uint32_t afr[2][4][4];
    #pragma unroll
    for (int mt = 0; mt < 2; mt++)
        #pragma unroll
        for (int ks = 0; ks < 4; ks++)
            ldsm_x4(afr[mt][ks][0], afr[mt][ks][1], afr[mt][ks][2], afr[mt][ks][3],
                    a_base + mt * 16 * ROWB + ((((ks << 1) + ap) ^ a_swz) << 4));

    float rsum[4] = {0.f, 0.f, 0.f, 0.f};

    for (int i = 0; i < NCH; i++) {
        const int s = i & 1;
        if (i + 1 < NCH) {
            const signed char* Mc = Msrc + (size_t)(i + 1) * TILE_C * DDIM;
            const uint32_t dst = sb + (s ? SM_M0 : SM_M1);
            #pragma unroll
            for (int j = 0; j < 2; j++) {
                int u = tid + j * 256;
                int row = u >> 3, un = u & 7;
                CP_ASYNC16(dst + row * ROWB + ((un ^ (row & 7)) << 4),
                           Mc + row * DDIM + un * 16);
            }
            CP_COMMIT();
            CP_WAIT1();
        } else {
            CP_WAIT0();
        }
        __syncthreads();

        const uint32_t mb = sb + (s ? SM_M1 : SM_M0);

        int c[2][4][4];
        #pragma unroll
        for (int mt = 0; mt < 2; mt++)
            #pragma unroll
            for (int nt = 0; nt < 4; nt++)
                #pragma unroll
                for (int q = 0; q < 4; q++) c[mt][nt][q] = MAGICI;

        #pragma unroll
        for (int ks = 0; ks < 4; ks++) {
            uint32_t b[2][4];
            const uint32_t uo = (((ks << 1) + bp) ^ b_swz) << 4;
            ldsm_x4(b[0][0], b[0][1], b[0][2], b[0][3], mb + b_off0 + uo);
            ldsm_x4(b[1][0], b[1][1], b[1][2], b[1][3], mb + b_off1 + uo);
            #pragma unroll
            for (int mt = 0; mt < 2; mt++) {
                #pragma unroll
                for (int h = 0; h < 2; h++) {
                    mma_s8(c[mt][h*2+0][0], c[mt][h*2+0][1], c[mt][h*2+0][2], c[mt][h*2+0][3],
                           afr[mt][ks][0], afr[mt][ks][1], afr[mt][ks][2], afr[mt][ks][3],
                           b[h][0], b[h][1]);
                    mma_s8(c[mt][h*2+1][0], c[mt][h*2+1][1], c[mt][h*2+1][2], c[mt][h*2+1][3],
                           afr[mt][ks][0], afr[mt][ks][1], afr[mt][ks][2], afr[mt][ks][3],
                           b[h][2], b[h][3]);
                }
            }
        }
        __syncthreads();

        // epilogue: magic-bias FFMA (f32) -> pack f16x2 -> ex2.f16x2 -> HADD2
        const int colbase = i * TILE_C + wn * 32 + ((lane & 3) << 1);
        float2 sv[4], bv[4];
        #pragma unroll
        for (int nt = 0; nt < 4; nt++) {
            float2 v = *reinterpret_cast<const float2*>(ic + colbase + nt * 8);
            sv[nt].x = v.x * INVQ;          sv[nt].y = v.y * INVQ;
            bv[nt].x = -MAGICF * sv[nt].x;  bv[nt].y = -MAGICF * sv[nt].y;
        }
        uint32_t acch[4] = {0u, 0u, 0u, 0u};   // f16x2 accumulators (per-chunk)
        #pragma unroll
        for (int mt = 0; mt < 2; mt++)
            #pragma unroll
            for (int nt = 0; nt < 4; nt++) {
                float e0 = fmaf(__int_as_float(c[mt][nt][0]), sv[nt].x, bv[nt].x);
                float e1 = fmaf(__int_as_float(c[mt][nt][1]), sv[nt].y, bv[nt].y);
                float e2 = fmaf(__int_as_float(c[mt][nt][2]), sv[nt].x, bv[nt].x);
                float e3 = fmaf(__int_as_float(c[mt][nt][3]), sv[nt].y, bv[nt].y);
                acch[mt*2+0] = hadd2u(acch[mt*2+0], ex2_h2(pack_h2(e0, e1)));
                acch[mt*2+1] = hadd2u(acch[mt*2+1], ex2_h2(pack_h2(e2, e3)));
            }
        #pragma unroll
        for (int q = 0; q < 4; q++) {
            float2 f = __half22float2(*reinterpret_cast<__half2*>(&acch[q]));
            rsum[q] += f.x + f.y;
        }
    }

    // reduce row sums: quad shfl, then cross-warp smem atomics
    #pragma unroll
    for (int i = 0; i < 4; i++) {
        rsum[i] += __shfl_xor_sync(0xFFFFFFFFu, rsum[i], 1);
        rsum[i] += __shfl_xor_sync(0xFFFFFFFFu, rsum[i], 2);
    }
    if ((lane & 3) == 0) {
        const int r0 = wm * 32 + (lane >> 2);
        atomicAdd(red + r0 + 0,  rsum[0]);
        atomicAdd(red + r0 + 8,  rsum[1]);
        atomicAdd(red + r0 + 16, rsum[2]);
        atomicAdd(red + r0 + 24, rsum[3]);
    }
    __syncthreads();       // red[] = S per sample

    // ---- fused positive logit + per-CTA partial (exact fp32) ----
    float psum = 0.f;
    const int b0 = bx * TILE_B;
    #pragma unroll 4
    for (int j = 0; j < 16; j++) {
        const int bl  = wid * 16 + j;
        const int bgl = b0 + bl;
        const int l = lab[bgl];
        float4 f = reinterpret_cast<const float4*>(F + (size_t)bgl * DDIM)[lane];
        float4 m = reinterpret_cast<const float4*>(Mf + (size_t)l * DDIM)[lane];
        float d = f.x * m.x + f.y * m.y + f.z * m.z + f.w * m.w;
        #pragma unroll
        for (int o = 16; o > 0; o >>= 1) d += __shfl_xor_sync(0xFFFFFFFFu, d, o);
        if (lane == 0)
            psum += d * ic[l] * LN2F - logf(red[bl]);
    }
    if (lane == 0) ws[wid] = psum;
    __syncthreads();

    // ---- per-CTA partial + last-block full reduction ----
    if (tid == 0) {
        float s = 0.f;
        #pragma unroll
        for (int i = 0; i < 8; i++) s += ws[i];
        g_part[side * (BB / TILE_B) + bx] = s;
        __threadfence();
        unsigned int v = atomicAdd(&g_cnt, 1u);
        *flg = (v == NBLK - 1) ? 1u : 0u;
    }
    __syncthreads();

    if (*flg) {
        float* smr = ic;
        smr[tid] = *((volatile float*)g_part + tid);
        __syncthreads();
        for (int st = 128; st > 0; st >>= 1) {
            if (tid < st) smr[tid] += smr[tid + st];
            __syncthreads();
        }
        if (tid == 0) {
            int iv = lbp[0];
            float lbv = (iv > 1000000 || iv < -1000000) ? __int_as_float(iv) : (float)iv;
            out[0] = (-lbv) * 0.5f / (float)BB * smr[0];
            g_cnt = 0;
        }
    }
}

// ---------------- launch ----------------
extern "C" void kernel_launch(void* const* d_in, const int* in_sizes, int n_in,
                              void* d_out, int out_size)
{
    const float* features       = (const float*)d_in[0];
    const float* features_I     = (const float*)d_in[1];
    const float* M_kmeans       = (const float*)d_in[2];
    const float* M_kmeans_I     = (const float*)d_in[3];
    const float* concentrations = (const float*)d_in[4];
    const float* concentr_I     = (const float*)d_in[5];
    const int*   labels         = (const int*)d_in[6];
    const int*   labels_I       = (const int*)d_in[7];
    const int*   lb             = (n_in > 8) ? (const int*)d_in[8] : nullptr;
    float* out = (float*)d_out;

    convM_kernel<<<(2 * CC * DDIM / 16) / 256, 256>>>(M_kmeans, M_kmeans_I);

    cudaFuncSetAttribute(main_kernel,
                         cudaFuncAttributeMaxDynamicSharedMemorySize, SM_TOT);
    main_kernel<<<dim3(BB / TILE_B, 2), 256, SM_TOT>>>(
        features, features_I, M_kmeans, M_kmeans_I,
        concentrations, concentr_I, labels, labels_I, lb, out);
}